// round 3
// baseline (speedup 1.0000x reference)
#include <cuda_runtime.h>
#include <cuda_bf16.h>

// Problem constants
#define B_    32
#define H_    128
#define SKV_  8192
#define D_    576      // DIM + TAIL
#define DIMV_ 512      // value/output dim
#define TOPK_ 2048
#define QPOS_ 8191
#define SCALE_ 0.041666666666666664f   // 1/sqrt(576)

// Tiling
#define HT      16              // heads per CTA
#define NW      8               // warps per CTA (2 heads per warp)
#define KT      32              // keys per tile
#define NTILES  (TOPK_ / KT)    // 64
#define PAD_ROW 580             // floats per smem row (576 + 4 pad; 145 float4, stride%8==1 -> conflict-free)

#define SMEM_FLOATS ((KT + HT) * PAD_ROW)
#define SMEM_BYTES  (SMEM_FLOATS * 4)

__global__ __launch_bounds__(256, 2)
void sparse_mla_decode_kernel(const float* __restrict__ Qg,
                              const float* __restrict__ KVg,
                              const int*   __restrict__ Idx,
                              float*       __restrict__ Out)
{
    extern __shared__ float smem[];
    float* Ks = smem;                      // [KT][PAD_ROW]
    float* Qs = smem + KT * PAD_ROW;       // [HT][PAD_ROW]

    const int b    = blockIdx.y;
    const int hg   = blockIdx.x;           // head group 0..7
    const int tid  = threadIdx.x;
    const int lane = tid & 31;
    const int w    = tid >> 5;             // warp 0..7

    // ---- Load Q for this CTA's 16 heads into smem (float4, coalesced) ----
    {
        const int row = tid >> 4;          // 0..15
        const int sub = tid & 15;
        const float4* src = (const float4*)(Qg + ((size_t)b * H_ + hg * HT + row) * D_);
        float4* dst = (float4*)(Qs + row * PAD_ROW);
        #pragma unroll
        for (int j = 0; j < 9; j++)        // 144 float4 per row / 16 threads
            dst[sub + 16 * j] = src[sub + 16 * j];
    }

    const int h0 = hg * HT + 2 * w;        // this warp's first head
    const float4* Qr0 = (const float4*)(Qs + (2 * w)     * PAD_ROW);
    const float4* Qr1 = (const float4*)(Qs + (2 * w + 1) * PAD_ROW);
    const int* idx_base = Idx + b * TOPK_;

    float acc0[16], acc1[16];
    #pragma unroll
    for (int j = 0; j < 16; j++) { acc0[j] = 0.f; acc1[j] = 0.f; }
    float m0 = -1e30f, m1 = -1e30f, l0 = 0.f, l1 = 0.f;

    for (int t = 0; t < NTILES; t++) {
        __syncthreads();   // previous tile's AV reads done before overwrite
        // ---- Gather 32 KV rows into smem (8 threads per row, float4) ----
        {
            const int row = tid >> 3;      // 0..31
            const int sub = tid & 7;
            const int kidx = idx_base[t * KT + row];
            const float4* src = (const float4*)(KVg + ((size_t)b * SKV_ + kidx) * D_);
            float4* dst = (float4*)(Ks + row * PAD_ROW);
            #pragma unroll
            for (int j = 0; j < 18; j++)   // 144 float4 per row / 8 threads
                dst[sub + 8 * j] = src[sub + 8 * j];
        }
        __syncthreads();

        // ---- Scores: lane computes key `lane` for both heads ----
        const float4* Kr = (const float4*)(Ks + lane * PAD_ROW);
        float s0 = 0.f, s1 = 0.f;
        #pragma unroll 8
        for (int i = 0; i < 144; i++) {
            float4 kv = Kr[i];             // conflict-free (stride 145 f4)
            float4 q0 = Qr0[i];            // warp broadcast
            float4 q1 = Qr1[i];            // warp broadcast
            s0 = fmaf(kv.x, q0.x, s0); s0 = fmaf(kv.y, q0.y, s0);
            s0 = fmaf(kv.z, q0.z, s0); s0 = fmaf(kv.w, q0.w, s0);
            s1 = fmaf(kv.x, q1.x, s1); s1 = fmaf(kv.y, q1.y, s1);
            s1 = fmaf(kv.z, q1.z, s1); s1 = fmaf(kv.w, q1.w, s1);
        }
        s0 *= SCALE_; s1 *= SCALE_;

        {   // causal/range mask (always true for this shape, kept for generality)
            const int kidx = idx_base[t * KT + lane];
            if (!((kidx <= QPOS_) && (kidx < SKV_))) { s0 = -1e30f; s1 = -1e30f; }
        }

        // ---- Online softmax (per warp, 2 heads) ----
        float tm0 = s0, tm1 = s1;
        #pragma unroll
        for (int off = 16; off > 0; off >>= 1) {
            tm0 = fmaxf(tm0, __shfl_xor_sync(0xffffffffu, tm0, off));
            tm1 = fmaxf(tm1, __shfl_xor_sync(0xffffffffu, tm1, off));
        }
        const float nm0 = fmaxf(m0, tm0), nm1 = fmaxf(m1, tm1);
        const float p0 = __expf(s0 - nm0), p1 = __expf(s1 - nm1);
        float ts0 = p0, ts1 = p1;
        #pragma unroll
        for (int off = 16; off > 0; off >>= 1) {
            ts0 += __shfl_xor_sync(0xffffffffu, ts0, off);
            ts1 += __shfl_xor_sync(0xffffffffu, ts1, off);
        }
        const float a0 = __expf(m0 - nm0), a1 = __expf(m1 - nm1);
        l0 = l0 * a0 + ts0; l1 = l1 * a1 + ts1;
        m0 = nm0; m1 = nm1;
        #pragma unroll
        for (int j = 0; j < 16; j++) { acc0[j] *= a0; acc1[j] *= a1; }

        // ---- AV accumulate: lane owns dims {lane + 32j}, shares V loads across 2 heads ----
        #pragma unroll 2
        for (int k = 0; k < KT; k++) {
            const float pk0 = __shfl_sync(0xffffffffu, p0, k);
            const float pk1 = __shfl_sync(0xffffffffu, p1, k);
            const float* V = Ks + k * PAD_ROW + lane;
            #pragma unroll
            for (int j = 0; j < 16; j++) {
                const float v = V[32 * j];          // coalesced, conflict-free
                acc0[j] = fmaf(pk0, v, acc0[j]);
                acc1[j] = fmaf(pk1, v, acc1[j]);
            }
        }
    }

    // ---- Epilogue ----
    const float inv0 = 1.0f / l0, inv1 = 1.0f / l1;
    float* O0 = Out + ((size_t)b * H_ + h0) * DIMV_;
    float* O1 = O0 + DIMV_;
    #pragma unroll
    for (int j = 0; j < 16; j++) {
        O0[lane + 32 * j] = acc0[j] * inv0;
        O1[lane + 32 * j] = acc1[j] * inv1;
    }
}

extern "C" void kernel_launch(void* const* d_in, const int* in_sizes, int n_in,
                              void* d_out, int out_size)
{
    const float* Q   = (const float*)d_in[0];
    const float* KV  = (const float*)d_in[1];
    const int*   Idx = (const int*)d_in[2];
    float*       Out = (float*)d_out;

    cudaFuncSetAttribute(sparse_mla_decode_kernel,
                         cudaFuncAttributeMaxDynamicSharedMemorySize, SMEM_BYTES);

    dim3 grid(H_ / HT, B_);   // (8, 32) = 256 CTAs
    dim3 block(256);
    sparse_mla_decode_kernel<<<grid, block, SMEM_BYTES>>>(Q, KV, Idx, Out);
}

// round 6
// speedup vs baseline: 3.7378x; 3.7378x over previous
#include <cuda_runtime.h>
#include <cuda_bf16.h>
#include <cstdint>

// ---------------- Problem constants ----------------
#define B_    32
#define H_    128
#define SKV_  8192
#define D_    576      // DIM + TAIL (score dim)
#define DIMV_ 512      // value/output dim
#define TOPK_ 2048
#define SCALE_ 0.041666666666666664f   // 1/sqrt(576)

// ---------------- Tiling ----------------
#define HT    32              // heads per CTA
#define KT    32              // keys per tile
#define NTILES (TOPK_ / KT)   // 64

// smem pitches (in 32-bit words)
#define PQW  292              // Q/K row pitch: 584 bf16 = 292 words (292%32==4 -> conflict-free frags)
#define PS   36               // score buffer pitch (floats)
#define PPW  20               // P row pitch: 40 bf16 = 20 words (20g+t distinct banks)

// smem word offsets
#define OFF_QH   0
#define OFF_QL   (OFF_QH + HT * PQW)        // 9344
#define OFF_KH   (OFF_QL + HT * PQW)        // 18688
#define OFF_KL   (OFF_KH + KT * PQW)        // 28032
#define OFF_SB0  (OFF_KL + KT * PQW)        // 37376
#define OFF_SB1  (OFF_SB0 + HT * PS)        // 38528
#define OFF_PH   (OFF_SB1 + HT * PS)        // 39680
#define OFF_PL   (OFF_PH + HT * PPW)        // 40320
#define OFF_ALPHA (OFF_PL + HT * PPW)       // 40960
#define OFF_LINV  (OFF_ALPHA + 32)          // 40992
#define SMEM_WORDS (OFF_LINV + 32)          // 41024
#define SMEM_BYTES (SMEM_WORDS * 4)         // 164096

#define QL_OFF (OFF_QL - OFF_QH)            // 9344 (word delta hi->lo)
#define KL_OFF (OFF_KL - OFF_KH)            // 9344
#define PL_OFF (OFF_PL - OFF_PH)            // 640

// ---------------- PTX helpers ----------------
__device__ __forceinline__ void mma_bf16(float* d, const uint32_t* a, uint32_t b0, uint32_t b1) {
    asm volatile(
        "mma.sync.aligned.m16n8k16.row.col.f32.bf16.bf16.f32 "
        "{%0,%1,%2,%3},{%4,%5,%6,%7},{%8,%9},{%0,%1,%2,%3};"
        : "+f"(d[0]), "+f"(d[1]), "+f"(d[2]), "+f"(d[3])
        : "r"(a[0]), "r"(a[1]), "r"(a[2]), "r"(a[3]), "r"(b0), "r"(b1));
}

__device__ __forceinline__ void ldsm4t(uint32_t* r, uint32_t saddr) {
    asm volatile("ldmatrix.sync.aligned.m8n8.x4.trans.shared.b16 {%0,%1,%2,%3}, [%4];"
                 : "=r"(r[0]), "=r"(r[1]), "=r"(r[2]), "=r"(r[3]) : "r"(saddr));
}

__device__ __forceinline__ uint32_t pkbf(__nv_bfloat16 lo, __nv_bfloat16 hi) {
    __nv_bfloat162 v = __halves2bfloat162(lo, hi);
    return *reinterpret_cast<uint32_t*>(&v);
}

// split pair of fp32 into (hi, lo) bf16x2 words
__device__ __forceinline__ void split2(float x, float y, uint32_t& h, uint32_t& l) {
    __nv_bfloat16 hx = __float2bfloat16(x);
    __nv_bfloat16 hy = __float2bfloat16(y);
    float rx = x - __bfloat162float(hx);
    float ry = y - __bfloat162float(hy);
    h = pkbf(hx, hy);
    l = pkbf(__float2bfloat16(rx), __float2bfloat16(ry));
}

// ---------------- Kernel ----------------
__global__ __launch_bounds__(256, 1)
void sparse_mla_mma_kernel(const float* __restrict__ Qg,
                           const float* __restrict__ KVg,
                           const int*   __restrict__ Idx,
                           float*       __restrict__ Out)
{
    extern __shared__ uint32_t sm[];
    uint32_t* Qh = sm + OFF_QH;
    uint32_t* Kh = sm + OFF_KH;
    float*    Sb0 = (float*)(sm + OFF_SB0);
    float*    Sb1 = (float*)(sm + OFF_SB1);
    uint32_t* Ph = sm + OFF_PH;
    uint32_t* Pl = sm + OFF_PL;
    float*    alpha = (float*)(sm + OFF_ALPHA);
    float*    linv  = (float*)(sm + OFF_LINV);

    const int b   = blockIdx.y;
    const int hg  = blockIdx.x;
    const int tid = threadIdx.x;
    const int lane = tid & 31;
    const int w    = tid >> 5;
    const int g    = lane >> 2;     // fragment group row
    const int t4   = lane & 3;      // fragment group col

    // score-phase warp decomposition: mw (M half), nw (N half), dw (D half)
    const int mw = w & 1;
    const int nw = (w >> 1) & 1;
    const int dw = w >> 2;
    // AV-phase: warp owns dims [64w, 64w+64)
    const int dv = w * 64;

    // ---- Load + split Q (32 heads x 576) ----
    {
        const int row = tid >> 3;           // 0..31
        const int sub = tid & 7;
        const float4* src = (const float4*)(Qg + ((size_t)b * H_ + hg * HT + row) * D_);
        #pragma unroll
        for (int j = 0; j < 18; j++) {
            const int f4i = sub + 8 * j;    // 0..143
            float4 v = src[f4i];
            uint32_t h01, l01, h23, l23;
            split2(v.x, v.y, h01, l01);
            split2(v.z, v.w, h23, l23);
            const int base = row * PQW + 2 * f4i;
            *(uint2*)&Qh[base]          = make_uint2(h01, h23);
            *(uint2*)&Qh[base + QL_OFF] = make_uint2(l01, l23);
        }
    }

    // output accumulators: [mtile][ntile(8 dims each)][frag]
    float acc[2][8][4];
    #pragma unroll
    for (int m = 0; m < 2; m++)
        #pragma unroll
        for (int j = 0; j < 8; j++)
            #pragma unroll
            for (int c = 0; c < 4; c++) acc[m][j][c] = 0.f;

    // softmax state: this lane serves head = 4*w + (lane>>3); replicated across 8 lanes
    float mrow = -1e30f, lrow = 0.f;
    const int sm_head = 4 * w + (lane >> 3);
    const int ks8 = lane & 7;

    const int* idx_b = Idx + b * TOPK_;

    // precompute ldmatrix lane geometry (AV B-frags)
    const int lm_rowk = lane & 15;          // + 16*kk
    const int lm_coln = 8 * (lane >> 4);    // + dv + 16*jp

    for (int t = 0; t < NTILES; t++) {
        __syncthreads();   // previous AV done reading K/P

        // ---- Gather + split K tile (32 keys x 576) ----
        {
            const int row = tid >> 3;
            const int sub = tid & 7;
            const int kidx = idx_b[t * KT + row];
            const float4* src = (const float4*)(KVg + ((size_t)b * SKV_ + kidx) * D_);
            #pragma unroll
            for (int j = 0; j < 18; j++) {
                const int f4i = sub + 8 * j;
                float4 v = src[f4i];
                uint32_t h01, l01, h23, l23;
                split2(v.x, v.y, h01, l01);
                split2(v.z, v.w, h23, l23);
                const int base = row * PQW + 2 * f4i;
                *(uint2*)&Kh[base]          = make_uint2(h01, h23);
                *(uint2*)&Kh[base + KL_OFF] = make_uint2(l01, l23);
            }
        }
        __syncthreads();

        // ---- Score GEMM: warp computes 16 heads x 16 keys over its D-half ----
        float sacc[2][4];
        #pragma unroll
        for (int j = 0; j < 2; j++)
            #pragma unroll
            for (int c = 0; c < 4; c++) sacc[j][c] = 0.f;

        {
            const int aRow = 16 * mw + g;
            #pragma unroll 2
            for (int ks = 0; ks < 18; ks++) {
                const int kb2 = 144 * dw + 8 * ks;   // word col base
                const uint32_t* qp = Qh + aRow * PQW + kb2 + t4;
                uint32_t ah[4], al[4];
                ah[0] = qp[0];            ah[1] = qp[8 * PQW];
                ah[2] = qp[4];            ah[3] = qp[8 * PQW + 4];
                al[0] = qp[QL_OFF];       al[1] = qp[QL_OFF + 8 * PQW];
                al[2] = qp[QL_OFF + 4];   al[3] = qp[QL_OFF + 8 * PQW + 4];
                #pragma unroll
                for (int j = 0; j < 2; j++) {
                    const int krow = 16 * nw + 8 * j + g;
                    const uint32_t* kp = Kh + krow * PQW + kb2 + t4;
                    uint32_t bh0 = kp[0], bh1 = kp[4];
                    uint32_t bl0 = kp[KL_OFF], bl1 = kp[KL_OFF + 4];
                    mma_bf16(sacc[j], ah, bh0, bh1);
                    mma_bf16(sacc[j], ah, bl0, bl1);
                    mma_bf16(sacc[j], al, bh0, bh1);
                }
            }
        }
        // store partial scores (per D-half buffer)
        {
            float* Sb = dw ? Sb1 : Sb0;
            const int row0 = 16 * mw + g;
            #pragma unroll
            for (int j = 0; j < 2; j++) {
                const int col = 16 * nw + 8 * j + 2 * t4;
                Sb[row0 * PS + col]       = sacc[j][0];
                Sb[row0 * PS + col + 1]   = sacc[j][1];
                Sb[(row0 + 8) * PS + col]     = sacc[j][2];
                Sb[(row0 + 8) * PS + col + 1] = sacc[j][3];
            }
        }
        __syncthreads();

        // ---- Softmax (online): lane group of 8 per head, 4 keys per lane ----
        {
            float4 sA = *(const float4*)&Sb0[sm_head * PS + 4 * ks8];
            float4 sB = *(const float4*)&Sb1[sm_head * PS + 4 * ks8];
            float s0 = (sA.x + sB.x) * SCALE_;
            float s1 = (sA.y + sB.y) * SCALE_;
            float s2 = (sA.z + sB.z) * SCALE_;
            float s3 = (sA.w + sB.w) * SCALE_;
            float tm = fmaxf(fmaxf(s0, s1), fmaxf(s2, s3));
            #pragma unroll
            for (int off = 1; off < 8; off <<= 1)
                tm = fmaxf(tm, __shfl_xor_sync(0xffffffffu, tm, off));
            const float newm = fmaxf(mrow, tm);
            const float p0 = __expf(s0 - newm);
            const float p1 = __expf(s1 - newm);
            const float p2 = __expf(s2 - newm);
            const float p3 = __expf(s3 - newm);
            float ts = p0 + p1 + p2 + p3;
            #pragma unroll
            for (int off = 1; off < 8; off <<= 1)
                ts += __shfl_xor_sync(0xffffffffu, ts, off);
            const float afac = __expf(mrow - newm);
            lrow = lrow * afac + ts;
            mrow = newm;
            if (ks8 == 0) alpha[sm_head] = afac;
            // split P to bf16 hi/lo and store
            uint32_t h01, l01, h23, l23;
            split2(p0, p1, h01, l01);
            split2(p2, p3, h23, l23);
            const int base = sm_head * PPW + 2 * ks8;
            *(uint2*)&Ph[base]          = make_uint2(h01, h23);
            *(uint2*)&Ph[base + PL_OFF] = make_uint2(l01, l23);
        }
        __syncthreads();

        // ---- AV: rescale accs, then P(32xKT) x V(KTx64-dims-of-warp) ----
        {
            const float f0 = alpha[g],      f1 = alpha[g + 8];
            const float f2 = alpha[16 + g], f3 = alpha[24 + g];
            #pragma unroll
            for (int j = 0; j < 8; j++) {
                #pragma unroll
                for (int m = 0; m < 2; m++) {
                    const float fa = m ? f2 : f0;
                    const float fb = m ? f3 : f1;
                    acc[m][j][0] *= fa; acc[m][j][1] *= fa;
                    acc[m][j][2] *= fb; acc[m][j][3] *= fb;
                }
            }
            #pragma unroll
            for (int kk = 0; kk < 2; kk++) {
                uint32_t pah[2][4], pal[2][4];
                #pragma unroll
                for (int m = 0; m < 2; m++) {
                    const uint32_t* pp = Ph + (16 * m + g) * PPW + 8 * kk + t4;
                    pah[m][0] = pp[0];            pah[m][1] = pp[8 * PPW];
                    pah[m][2] = pp[4];            pah[m][3] = pp[8 * PPW + 4];
                    pal[m][0] = pp[PL_OFF];       pal[m][1] = pp[PL_OFF + 8 * PPW];
                    pal[m][2] = pp[PL_OFF + 4];   pal[m][3] = pp[PL_OFF + 8 * PPW + 4];
                }
                #pragma unroll
                for (int jp = 0; jp < 4; jp++) {
                    const int rowk = 16 * kk + lm_rowk;
                    const int coln = dv + 16 * jp + lm_coln;
                    const uint32_t* vp = Kh + rowk * PQW + (coln >> 1);
                    const uint32_t sah = (uint32_t)__cvta_generic_to_shared(vp);
                    uint32_t bh[4], bl[4];
                    ldsm4t(bh, sah);
                    ldsm4t(bl, sah + KL_OFF * 4);
                    #pragma unroll
                    for (int m = 0; m < 2; m++) {
                        mma_bf16(acc[m][2 * jp],     pah[m], bh[0], bh[1]);
                        mma_bf16(acc[m][2 * jp],     pah[m], bl[0], bl[1]);
                        mma_bf16(acc[m][2 * jp],     pal[m], bh[0], bh[1]);
                        mma_bf16(acc[m][2 * jp + 1], pah[m], bh[2], bh[3]);
                        mma_bf16(acc[m][2 * jp + 1], pah[m], bl[2], bl[3]);
                        mma_bf16(acc[m][2 * jp + 1], pal[m], bh[2], bh[3]);
                    }
                }
            }
        }
    }

    // ---- Epilogue ----
    if (ks8 == 0) linv[sm_head] = 1.0f / lrow;
    __syncthreads();
    {
        const float i0 = linv[g],      i1 = linv[g + 8];
        const float i2 = linv[16 + g], i3 = linv[24 + g];
        #pragma unroll
        for (int m = 0; m < 2; m++) {
            const float fa = m ? i2 : i0;
            const float fb = m ? i3 : i1;
            const int row0 = 16 * m + g;
            #pragma unroll
            for (int j = 0; j < 8; j++) {
                const int dim = dv + 8 * j + 2 * t4;
                float* o0 = Out + ((size_t)b * H_ + hg * HT + row0) * DIMV_ + dim;
                float* o1 = Out + ((size_t)b * H_ + hg * HT + row0 + 8) * DIMV_ + dim;
                *(float2*)o0 = make_float2(acc[m][j][0] * fa, acc[m][j][1] * fa);
                *(float2*)o1 = make_float2(acc[m][j][2] * fb, acc[m][j][3] * fb);
            }
        }
    }
}

extern "C" void kernel_launch(void* const* d_in, const int* in_sizes, int n_in,
                              void* d_out, int out_size)
{
    const float* Q   = (const float*)d_in[0];
    const float* KV  = (const float*)d_in[1];
    const int*   Idx = (const int*)d_in[2];
    float*       Out = (float*)d_out;

    cudaFuncSetAttribute(sparse_mla_mma_kernel,
                         cudaFuncAttributeMaxDynamicSharedMemorySize, SMEM_BYTES);

    dim3 grid(H_ / HT, B_);   // (4, 32) = 128 CTAs -> one wave
    dim3 block(256);
    sparse_mla_mma_kernel<<<grid, block, SMEM_BYTES>>>(Q, KV, Idx, Out);
}

// round 8
// speedup vs baseline: 3.9403x; 1.0542x over previous
#include <cuda_runtime.h>
#include <cuda_bf16.h>
#include <cstdint>

// ---------------- Problem constants ----------------
#define B_    32
#define H_    128
#define SKV_  8192
#define D_    576      // DIM + TAIL (score dim)
#define DIMV_ 512      // value/output dim
#define TOPK_ 2048
#define SCALE_ 0.041666666666666664f   // 1/sqrt(576)

// ---------------- Tiling ----------------
#define HT    32              // heads per CTA
#define KT    32              // keys per tile
#define NTILES (TOPK_ / KT)   // 64

// smem pitches (in 32-bit words)
#define PQW  292              // Q/K bf16 row pitch (584 bf16; 292%32==4 -> conflict-free frags)
#define PRAW 576              // raw fp32 staging row pitch
#define PS   36               // score/P buffer pitch (mult of 4 for float4; %32==4)
#define PPW  36               // P pitch == Sb pitch (aliased)

// smem word offsets
#define OFF_QH   0
#define OFF_QL   (OFF_QH + HT * PQW)        // 9344
#define OFF_KH   (OFF_QL + HT * PQW)        // 18688
#define OFF_KL   (OFF_KH + KT * PQW)        // 28032
#define OFF_RAW  (OFF_KL + KT * PQW)        // 37376
#define OFF_SB0  (OFF_RAW + KT * PRAW)      // 55808
#define OFF_SB1  (OFF_SB0 + HT * PS)        // 56960
#define SMEM_WORDS (OFF_SB1 + 31 * PS + 32) // 58108
#define SMEM_BYTES (SMEM_WORDS * 4)         // 232432 (<= 232448 limit)

#define QL_OFF (OFF_QL - OFF_QH)            // 9344
#define KL_OFF (OFF_KL - OFF_KH)            // 9344
#define PL_OFF (OFF_SB1 - OFF_SB0)          // 1152 (P-hi in Sb0, P-lo in Sb1)

// ---------------- PTX helpers ----------------
__device__ __forceinline__ void mma_bf16(float* d, const uint32_t* a, uint32_t b0, uint32_t b1) {
    asm volatile(
        "mma.sync.aligned.m16n8k16.row.col.f32.bf16.bf16.f32 "
        "{%0,%1,%2,%3},{%4,%5,%6,%7},{%8,%9},{%0,%1,%2,%3};"
        : "+f"(d[0]), "+f"(d[1]), "+f"(d[2]), "+f"(d[3])
        : "r"(a[0]), "r"(a[1]), "r"(a[2]), "r"(a[3]), "r"(b0), "r"(b1));
}

__device__ __forceinline__ void ldsm4t(uint32_t* r, uint32_t saddr) {
    asm volatile("ldmatrix.sync.aligned.m8n8.x4.trans.shared.b16 {%0,%1,%2,%3}, [%4];"
                 : "=r"(r[0]), "=r"(r[1]), "=r"(r[2]), "=r"(r[3]) : "r"(saddr));
}

__device__ __forceinline__ void cp16(uint32_t dst, const void* src) {
    asm volatile("cp.async.cg.shared.global [%0], [%1], 16;" :: "r"(dst), "l"(src));
}
__device__ __forceinline__ void cp_commit() { asm volatile("cp.async.commit_group;"); }
__device__ __forceinline__ void cp_wait_all() { asm volatile("cp.async.wait_group 0;"); }

__device__ __forceinline__ uint32_t pkbf(__nv_bfloat16 lo, __nv_bfloat16 hi) {
    __nv_bfloat162 v = __halves2bfloat162(lo, hi);
    return *reinterpret_cast<uint32_t*>(&v);
}

// split pair of fp32 into (hi, lo) bf16x2 words
__device__ __forceinline__ void split2(float x, float y, uint32_t& h, uint32_t& l) {
    __nv_bfloat16 hx = __float2bfloat16(x);
    __nv_bfloat16 hy = __float2bfloat16(y);
    float rx = x - __bfloat162float(hx);
    float ry = y - __bfloat162float(hy);
    h = pkbf(hx, hy);
    l = pkbf(__float2bfloat16(rx), __float2bfloat16(ry));
}

// ---------------- Kernel ----------------
__global__ __launch_bounds__(256, 1)
void sparse_mla_pipe_kernel(const float* __restrict__ Qg,
                            const float* __restrict__ KVg,
                            const int*   __restrict__ Idx,
                            float*       __restrict__ Out)
{
    extern __shared__ uint32_t sm[];
    uint32_t* Qh  = sm + OFF_QH;
    uint32_t* Kh  = sm + OFF_KH;
    float*    Raw = (float*)(sm + OFF_RAW);
    float*    Sb0 = (float*)(sm + OFF_SB0);
    float*    Sb1 = (float*)(sm + OFF_SB1);
    uint32_t* Ph  = sm + OFF_SB0;            // P-hi aliased into Sb0 (cols 0..19)
    float*    SbF = (float*)(sm + OFF_SB0);  // alpha/linv live at col 35 of Sb0 rows

    const int b   = blockIdx.y;
    const int hg  = blockIdx.x;
    const int tid = threadIdx.x;
    const int lane = tid & 31;
    const int w    = tid >> 5;
    const int g    = lane >> 2;
    const int t4   = lane & 3;

    // score-phase warp decomposition
    const int mw = w & 1;
    const int nw = (w >> 1) & 1;
    const int dw = w >> 2;
    const int dv = w * 64;                  // AV dim slice

    const int row = tid >> 3;               // gather/split row 0..31
    const int sub = tid & 7;
    const int* idx_b = Idx + b * TOPK_;
    const uint32_t raw_s = (uint32_t)__cvta_generic_to_shared(Raw + row * PRAW);

    // ---- Prologue: kick off async gather of tile 0, then load+split Q ----
    int pre_idx = idx_b[row];
    {
        const float* src = KVg + ((size_t)b * SKV_ + pre_idx) * D_;
        #pragma unroll
        for (int j = 0; j < 18; j++) {
            const int f4i = sub + 8 * j;
            cp16(raw_s + f4i * 16, src + 4 * f4i);
        }
        cp_commit();
    }
    pre_idx = idx_b[KT + row];              // idx for tile 1

    {
        const float4* src = (const float4*)(Qg + ((size_t)b * H_ + hg * HT + row) * D_);
        #pragma unroll
        for (int j = 0; j < 18; j++) {
            const int f4i = sub + 8 * j;
            float4 v = src[f4i];
            uint32_t h01, l01, h23, l23;
            split2(v.x, v.y, h01, l01);
            split2(v.z, v.w, h23, l23);
            const int base = row * PQW + 2 * f4i;
            *(uint2*)&Qh[base]          = make_uint2(h01, h23);
            *(uint2*)&Qh[base + QL_OFF] = make_uint2(l01, l23);
        }
    }

    float acc[2][8][4];
    #pragma unroll
    for (int m = 0; m < 2; m++)
        #pragma unroll
        for (int j = 0; j < 8; j++)
            #pragma unroll
            for (int c = 0; c < 4; c++) acc[m][j][c] = 0.f;

    float mrow = -1e30f, lrow = 0.f;
    const int sm_head = 4 * w + (lane >> 3);
    const int ks8 = lane & 7;

    const int lm_rowk = lane & 15;
    const int lm_coln = 8 * (lane >> 4);

    for (int t = 0; t < NTILES; t++) {
        cp_wait_all();        // this thread's gather(t) into Raw done
        __syncthreads();      // all threads' gather visible; AV(t-1) done with Kh/Kl

        // ---- Split pass: Raw (fp32) -> Kh/Kl (bf16 hi/lo) ----
        {
            const float4* rp = (const float4*)(Raw + row * PRAW);
            #pragma unroll
            for (int j = 0; j < 18; j++) {
                const int f4i = sub + 8 * j;
                float4 v = rp[f4i];
                uint32_t h01, l01, h23, l23;
                split2(v.x, v.y, h01, l01);
                split2(v.z, v.w, h23, l23);
                const int base = row * PQW + 2 * f4i;
                *(uint2*)&Kh[base]          = make_uint2(h01, h23);
                *(uint2*)&Kh[base + KL_OFF] = make_uint2(l01, l23);
            }
        }
        __syncthreads();      // split visible; Raw free for next gather

        // ---- Issue async gather of tile t+1 (overlaps compute below) ----
        if (t + 1 < NTILES) {
            const float* src = KVg + ((size_t)b * SKV_ + pre_idx) * D_;
            #pragma unroll
            for (int j = 0; j < 18; j++) {
                const int f4i = sub + 8 * j;
                cp16(raw_s + f4i * 16, src + 4 * f4i);
            }
            cp_commit();
            if (t + 2 < NTILES) pre_idx = idx_b[(t + 2) * KT + row];
        }

        // ---- Score GEMM: warp computes 16 heads x 16 keys over its D-half ----
        float sacc[2][4];
        #pragma unroll
        for (int j = 0; j < 2; j++)
            #pragma unroll
            for (int c = 0; c < 4; c++) sacc[j][c] = 0.f;

        {
            const int aRow = 16 * mw + g;
            #pragma unroll 2
            for (int ks = 0; ks < 18; ks++) {
                const int kb2 = 144 * dw + 8 * ks;
                const uint32_t* qp = Qh + aRow * PQW + kb2 + t4;
                uint32_t ah[4], al[4];
                ah[0] = qp[0];            ah[1] = qp[8 * PQW];
                ah[2] = qp[4];            ah[3] = qp[8 * PQW + 4];
                al[0] = qp[QL_OFF];       al[1] = qp[QL_OFF + 8 * PQW];
                al[2] = qp[QL_OFF + 4];   al[3] = qp[QL_OFF + 8 * PQW + 4];
                #pragma unroll
                for (int j = 0; j < 2; j++) {
                    const int krow = 16 * nw + 8 * j + g;
                    const uint32_t* kp = Kh + krow * PQW + kb2 + t4;
                    uint32_t bh0 = kp[0], bh1 = kp[4];
                    uint32_t bl0 = kp[KL_OFF], bl1 = kp[KL_OFF + 4];
                    mma_bf16(sacc[j], ah, bh0, bh1);
                    mma_bf16(sacc[j], ah, bl0, bl1);
                    mma_bf16(sacc[j], al, bh0, bh1);
                }
            }
        }
        {
            float* Sb = dw ? Sb1 : Sb0;
            const int row0 = 16 * mw + g;
            #pragma unroll
            for (int j = 0; j < 2; j++) {
                const int col = 16 * nw + 8 * j + 2 * t4;
                Sb[row0 * PS + col]           = sacc[j][0];
                Sb[row0 * PS + col + 1]       = sacc[j][1];
                Sb[(row0 + 8) * PS + col]     = sacc[j][2];
                Sb[(row0 + 8) * PS + col + 1] = sacc[j][3];
            }
        }
        __syncthreads();

        // ---- Softmax (online), P hi/lo written in place over Sb rows ----
        {
            float4 sA = *(const float4*)&Sb0[sm_head * PS + 4 * ks8];
            float4 sB = *(const float4*)&Sb1[sm_head * PS + 4 * ks8];
            float s0 = (sA.x + sB.x) * SCALE_;
            float s1 = (sA.y + sB.y) * SCALE_;
            float s2 = (sA.z + sB.z) * SCALE_;
            float s3 = (sA.w + sB.w) * SCALE_;
            float tm = fmaxf(fmaxf(s0, s1), fmaxf(s2, s3));
            #pragma unroll
            for (int off = 1; off < 8; off <<= 1)
                tm = fmaxf(tm, __shfl_xor_sync(0xffffffffu, tm, off));
            const float newm = fmaxf(mrow, tm);
            const float p0 = __expf(s0 - newm);
            const float p1 = __expf(s1 - newm);
            const float p2 = __expf(s2 - newm);
            const float p3 = __expf(s3 - newm);
            float ts = p0 + p1 + p2 + p3;
            #pragma unroll
            for (int off = 1; off < 8; off <<= 1)
                ts += __shfl_xor_sync(0xffffffffu, ts, off);
            const float afac = __expf(mrow - newm);
            lrow = lrow * afac + ts;
            mrow = newm;
            // writes below are warp-ordered after the float4 reads above
            if (ks8 == 0) SbF[sm_head * PS + 35] = afac;     // alpha in col 35
            uint32_t h01, l01, h23, l23;
            split2(p0, p1, h01, l01);
            split2(p2, p3, h23, l23);
            const int base = sm_head * PPW + 2 * ks8;
            *(uint2*)&Ph[base]          = make_uint2(h01, h23);
            *(uint2*)&Ph[base + PL_OFF] = make_uint2(l01, l23);
        }
        __syncthreads();

        // ---- AV: rescale accs, then P(32xKT) x V(KT x 64-dims-of-warp) ----
        {
            const float f0 = SbF[g * PS + 35],        f1 = SbF[(g + 8) * PS + 35];
            const float f2 = SbF[(16 + g) * PS + 35], f3 = SbF[(24 + g) * PS + 35];
            #pragma unroll
            for (int j = 0; j < 8; j++) {
                #pragma unroll
                for (int m = 0; m < 2; m++) {
                    const float fa = m ? f2 : f0;
                    const float fb = m ? f3 : f1;
                    acc[m][j][0] *= fa; acc[m][j][1] *= fa;
                    acc[m][j][2] *= fb; acc[m][j][3] *= fb;
                }
            }
            #pragma unroll
            for (int kk = 0; kk < 2; kk++) {
                uint32_t pah[2][4], pal[2][4];
                #pragma unroll
                for (int m = 0; m < 2; m++) {
                    const uint32_t* pp = Ph + (16 * m + g) * PPW + 8 * kk + t4;
                    pah[m][0] = pp[0];            pah[m][1] = pp[8 * PPW];
                    pah[m][2] = pp[4];            pah[m][3] = pp[8 * PPW + 4];
                    pal[m][0] = pp[PL_OFF];       pal[m][1] = pp[PL_OFF + 8 * PPW];
                    pal[m][2] = pp[PL_OFF + 4];   pal[m][3] = pp[PL_OFF + 8 * PPW + 4];
                }
                #pragma unroll
                for (int jp = 0; jp < 4; jp++) {
                    const int rowk = 16 * kk + lm_rowk;
                    const int coln = dv + 16 * jp + lm_coln;
                    const uint32_t* vp = Kh + rowk * PQW + (coln >> 1);
                    const uint32_t sah = (uint32_t)__cvta_generic_to_shared(vp);
                    uint32_t bh[4], bl[4];
                    ldsm4t(bh, sah);
                    ldsm4t(bl, sah + KL_OFF * 4);
                    #pragma unroll
                    for (int m = 0; m < 2; m++) {
                        mma_bf16(acc[m][2 * jp],     pah[m], bh[0], bh[1]);
                        mma_bf16(acc[m][2 * jp],     pah[m], bl[0], bl[1]);
                        mma_bf16(acc[m][2 * jp],     pal[m], bh[0], bh[1]);
                        mma_bf16(acc[m][2 * jp + 1], pah[m], bh[2], bh[3]);
                        mma_bf16(acc[m][2 * jp + 1], pah[m], bl[2], bl[3]);
                        mma_bf16(acc[m][2 * jp + 1], pal[m], bh[2], bh[3]);
                    }
                }
            }
        }
    }

    // ---- Epilogue (linv reuses alpha slots -> barrier before overwrite) ----
    __syncthreads();
    if (ks8 == 0) SbF[sm_head * PS + 35] = 1.0f / lrow;
    __syncthreads();
    {
        const float i0 = SbF[g * PS + 35],        i1 = SbF[(g + 8) * PS + 35];
        const float i2 = SbF[(16 + g) * PS + 35], i3 = SbF[(24 + g) * PS + 35];
        #pragma unroll
        for (int m = 0; m < 2; m++) {
            const float fa = m ? i2 : i0;
            const float fb = m ? i3 : i1;
            const int row0 = 16 * m + g;
            #pragma unroll
            for (int j = 0; j < 8; j++) {
                const int dim = dv + 8 * j + 2 * t4;
                float* o0 = Out + ((size_t)b * H_ + hg * HT + row0) * DIMV_ + dim;
                float* o1 = Out + ((size_t)b * H_ + hg * HT + row0 + 8) * DIMV_ + dim;
                *(float2*)o0 = make_float2(acc[m][j][0] * fa, acc[m][j][1] * fa);
                *(float2*)o1 = make_float2(acc[m][j][2] * fb, acc[m][j][3] * fb);
            }
        }
    }
}

extern "C" void kernel_launch(void* const* d_in, const int* in_sizes, int n_in,
                              void* d_out, int out_size)
{
    const float* Q   = (const float*)d_in[0];
    const float* KV  = (const float*)d_in[1];
    const int*   Idx = (const int*)d_in[2];
    float*       Out = (float*)d_out;

    cudaFuncSetAttribute(sparse_mla_pipe_kernel,
                         cudaFuncAttributeMaxDynamicSharedMemorySize, SMEM_BYTES);

    dim3 grid(H_ / HT, B_);   // (4, 32) = 128 CTAs -> one wave
    dim3 block(256);
    sparse_mla_pipe_kernel<<<grid, block, SMEM_BYTES>>>(Q, KV, Idx, Out);
}